// round 2
// baseline (speedup 1.0000x reference)
#include <cuda_runtime.h>
#include <cuda_bf16.h>

// PositionEmbeddingSine:
//  inputs (metadata order): coords [M,4] int32, sx, sy, sz, n_batches, max_len (int32 scalars)
//  output: [n_batches, max_len, 192] float32
//
// out[b, slot, d*64 + 2j + 0] = sin(q),  out[..., 2j+1] = cos(q)
//   q = coords[m, 1+d] * (2*pi / ((s_d - 1) + 1e-6)) * 10000^(-j/32)
//   b = coords[m,0], slot = m - first_occurrence_index(b)  (coords[:,0] is sorted)

#define SCALE_2PI 6.283185307179586f
#define EPS_F 1e-6f
// log2(10000) / 32
#define L2T_OVER_HALFF (13.287712379549449f / 32.0f)

__device__ int g_batch_start[4096];

__global__ void pes_starts_kernel(const int* __restrict__ coords, int M) {
    int m = blockIdx.x * blockDim.x + threadIdx.x;
    if (m >= M) return;
    int b = coords[4 * m];
    if (m == 0 || coords[4 * (m - 1)] != b) {
        if (b >= 0 && b < 4096) g_batch_start[b] = m;
    }
}

__global__ void __launch_bounds__(256) pes_main_kernel(
    const int* __restrict__ coords,
    const int* __restrict__ psx,
    const int* __restrict__ psy,
    const int* __restrict__ psz,
    const int* __restrict__ pml,
    float* __restrict__ out,
    int M)
{
    int p = blockIdx.x * blockDim.x + threadIdx.x;   // pair index, < M*96 (fits int32)
    int total = M * 96;
    if (p >= total) return;

    int m = p / 96;            // row
    int r = p - m * 96;        // 0..95
    int d = r >> 5;            // spatial dim 0..2
    int j = r & 31;            // frequency index 0..31

    int b     = __ldg(&coords[4 * m]);
    int val_i = __ldg(&coords[4 * m + 1 + d]);
    int s     = (d == 0) ? __ldg(psx) : (d == 1) ? __ldg(psy) : __ldg(psz);
    int max_len = __ldg(pml);

    int slot = m - g_batch_start[b];

    float inv_denom = SCALE_2PI / ((float)(s - 1) + EPS_F);
    float inv_dim   = exp2f(-(float)j * L2T_OVER_HALFF);  // 10000^(-j/32)
    float q = (float)val_i * inv_denom * inv_dim;

    float sn, cs;
    __sincosf(q, &sn, &cs);

    long long orow = (long long)b * max_len + slot;
    float2* o = (float2*)(out + orow * 192 + d * 64 + 2 * j);
    *o = make_float2(sn, cs);
}

extern "C" void kernel_launch(void* const* d_in, const int* in_sizes, int n_in,
                              void* d_out, int out_size)
{
    const int* coords = (const int*)d_in[0];
    const int* psx    = (const int*)d_in[1];
    const int* psy    = (const int*)d_in[2];
    const int* psz    = (const int*)d_in[3];
    // d_in[4] = n_batches (unused: batch ids come from coords)
    const int* pml    = (const int*)d_in[5];
    float* out        = (float*)d_out;

    int M = in_sizes[0] / 4;

    {
        int threads = 256;
        int blocks = (M + threads - 1) / threads;
        pes_starts_kernel<<<blocks, threads>>>(coords, M);
    }
    {
        int total = M * 96;
        int threads = 256;
        int blocks = (total + threads - 1) / threads;
        pes_main_kernel<<<blocks, threads>>>(coords, psx, psy, psz, pml, out, M);
    }
}

// round 3
// speedup vs baseline: 1.8478x; 1.8478x over previous
#include <cuda_runtime.h>
#include <cuda_bf16.h>

// PositionEmbeddingSine — warp-centric version.
// lane = frequency pair j (0..31); warp grid-strides over rows.
// out[b, slot, d*64 + 2j + {0,1}] = {sin,cos}( val_d * 2pi/((s_d-1)+eps) * 10000^(-j/32) )

#define SCALE_2PI 6.283185307179586f
#define EPS_F 1e-6f
// log2(10000)/32
#define L2T_OVER_32 (13.287712379549449f / 32.0f)

__device__ int g_batch_start[4096];

__global__ void pes_starts_kernel(const int* __restrict__ coords, int M) {
    int m = blockIdx.x * blockDim.x + threadIdx.x;
    if (m >= M) return;
    int b = coords[4 * m];
    if (m == 0 || coords[4 * (m - 1)] != b) {
        if (b >= 0 && b < 4096) g_batch_start[b] = m;
    }
}

__global__ void __launch_bounds__(256) pes_main_kernel(
    const int4* __restrict__ coords,   // [M] int4 rows: (b, x, y, z)
    const int* __restrict__ psx,
    const int* __restrict__ psy,
    const int* __restrict__ psz,
    const int* __restrict__ pml,
    float* __restrict__ out,
    int M)
{
    const int lane   = threadIdx.x & 31;
    const int warp   = (blockIdx.x * blockDim.x + threadIdx.x) >> 5;
    const int nwarps = (gridDim.x * blockDim.x) >> 5;

    const int max_len = __ldg(pml);

    // Per-thread loop invariants: combined scale for each spatial dim at this lane's freq.
    const float inv_dim = exp2f(-(float)lane * L2T_OVER_32);   // 10000^(-lane/32)
    const float fx = (SCALE_2PI / ((float)(__ldg(psx) - 1) + EPS_F)) * inv_dim;
    const float fy = (SCALE_2PI / ((float)(__ldg(psy) - 1) + EPS_F)) * inv_dim;
    const float fz = (SCALE_2PI / ((float)(__ldg(psz) - 1) + EPS_F)) * inv_dim;

    for (int m = warp; m < M; m += nwarps) {
        int4 c = __ldg(&coords[m]);                 // broadcast across warp
        int slot = m - g_batch_start[c.x];
        float* orow = out + ((long long)c.x * max_len + slot) * 192 + 2 * lane;

        float sn, cs;
        __sincosf((float)c.y * fx, &sn, &cs);
        *(float2*)(orow)       = make_float2(sn, cs);
        __sincosf((float)c.z * fy, &sn, &cs);
        *(float2*)(orow + 64)  = make_float2(sn, cs);
        __sincosf((float)c.w * fz, &sn, &cs);
        *(float2*)(orow + 128) = make_float2(sn, cs);
    }
}

extern "C" void kernel_launch(void* const* d_in, const int* in_sizes, int n_in,
                              void* d_out, int out_size)
{
    const int* coords = (const int*)d_in[0];
    const int* psx    = (const int*)d_in[1];
    const int* psy    = (const int*)d_in[2];
    const int* psz    = (const int*)d_in[3];
    // d_in[4] = n_batches (unused)
    const int* pml    = (const int*)d_in[5];
    float* out        = (float*)d_out;

    int M = in_sizes[0] / 4;

    {
        int threads = 256;
        int blocks = (M + threads - 1) / threads;
        pes_starts_kernel<<<blocks, threads>>>(coords, M);
    }
    {
        // One full-occupancy wave of persistent warps, grid-stride over rows.
        int threads = 256;
        int blocks = 148 * 8;
        pes_main_kernel<<<blocks, threads>>>((const int4*)coords, psx, psy, psz, pml, out, M);
    }
}